// round 15
// baseline (speedup 1.0000x reference)
#include <cuda_runtime.h>
#include <cuda_fp16.h>
#include <cstdint>
#include <cstddef>

// Problem constants
#define Bn 64
#define Sq 512
#define Dk 1024
#define Uo 4096
#define Ex 16

// Tiling: CTA covers 128m x 512n as TWO 128x256 tiles sharing one pipeline.
// Warp tile 64x64 (8 warps = 2m x 4n), 256 threads, BK=128, 2 stages.
#define BM 128
#define BN 256
#define BK 128
#define NK (Dk / BK)        // 8 k-iters per tile; 16 per CTA
#define NTHREADS 256
#define STAGES 2

// SMEM: halves, row stride 136 (272 B). Fragment LDS word = 68*row + c
// -> bank = (4*row + c) mod 32, conflict-free.
#define ST_H 136
#define A_TILE_B (BM * ST_H * 2)               // 34816
#define B_TILE_B (BN * ST_H * 2)               // 69632
#define STG_BYTES (A_TILE_B + B_TILE_B)        // 104448
#define BIAS_OFF (STAGES * STG_BYTES)          // 208896
#define SMEM_REQ (BIAS_OFF + 2 * BN * 4)       // 210944

// Device scratch: fp16 copies (x as-is, ws transposed to [e][n][k])
__device__ __half g_wsT[(size_t)Ex * Uo * Dk];   // 128 MB
__device__ __half g_x16[(size_t)Bn * Sq * Dk];   //  64 MB

// ---------------- helpers ----------------
__device__ __forceinline__ uint32_t smem_u32(const void* p) {
    uint32_t a;
    asm("{ .reg .u64 t; cvta.to.shared.u64 t, %1; cvt.u32.u64 %0, t; }"
        : "=r"(a) : "l"(p));
    return a;
}

__device__ __forceinline__ void cp16(uint32_t saddr, const void* g) {
    asm volatile("cp.async.cg.shared.global [%0], [%1], 16;" :: "r"(saddr), "l"(g));
}
__device__ __forceinline__ void cp_commit() {
    asm volatile("cp.async.commit_group;" ::: "memory");
}
template <int N>
__device__ __forceinline__ void cp_wait() {
    asm volatile("cp.async.wait_group %0;" :: "n"(N) : "memory");
}

__device__ __forceinline__ void mma_f16(float* d, const uint32_t* a, const uint32_t* b) {
    asm volatile(
        "mma.sync.aligned.m16n8k16.row.col.f32.f16.f16.f32 "
        "{%0,%1,%2,%3}, {%4,%5,%6,%7}, {%8,%9}, {%0,%1,%2,%3};"
        : "+f"(d[0]), "+f"(d[1]), "+f"(d[2]), "+f"(d[3])
        : "r"(a[0]), "r"(a[1]), "r"(a[2]), "r"(a[3]), "r"(b[0]), "r"(b[1]));
}

__device__ __forceinline__ void stcs8(float* p, float2 v) {
    asm volatile("st.global.cs.v2.f32 [%0], {%1, %2};" :: "l"(p), "f"(v.x), "f"(v.y)
                 : "memory");
}

// ---------------- pre-pass 1: ws [e][k][n] fp32 -> g_wsT [e][n][k] fp16 ----------------
__global__ void __launch_bounds__(256) transpose_h_kernel(const float* __restrict__ ws) {
    __shared__ uint32_t tileT2[32][37];   // [n][kpair], bank (5n+kp)%32, conflict-free
    const int e  = blockIdx.z;
    const int k0 = blockIdx.y * 64;
    const int n0 = blockIdx.x * 32;
    const int t  = threadIdx.x;

    const float* src = ws + ((size_t)e * Dk + k0) * Uo + n0;
    const int n  = t & 31;
    const int kp = t >> 5;
#pragma unroll
    for (int p = 0; p < 4; p++) {
        const int kk = (kp + p * 8) * 2;
        float v0 = src[(size_t)kk * Uo + n];
        float v1 = src[(size_t)(kk + 1) * Uo + n];
        __half2 h = __floats2half2_rn(v0, v1);
        tileT2[n][kp + p * 8] = *reinterpret_cast<uint32_t*>(&h);
    }
    __syncthreads();

    const int nn = t >> 3;
    const int j  = t & 7;
    __half* dst = g_wsT + ((size_t)e * Uo + n0 + nn) * Dk + k0;
    uint4 w;
    w.x = tileT2[nn][j * 4 + 0];
    w.y = tileT2[nn][j * 4 + 1];
    w.z = tileT2[nn][j * 4 + 2];
    w.w = tileT2[nn][j * 4 + 3];
    *reinterpret_cast<uint4*>(dst + j * 8) = w;
}

// ---------------- pre-pass 2: x fp32 -> fp16 ----------------
__global__ void __launch_bounds__(256) cvt_h_kernel(const float4* __restrict__ src,
                                                    uint2* __restrict__ dst, size_t n4) {
    size_t i = (size_t)blockIdx.x * blockDim.x + threadIdx.x;
    size_t stride = (size_t)gridDim.x * blockDim.x;
    for (; i < n4; i += stride) {
        float4 v = src[i];
        __half2 lo = __floats2half2_rn(v.x, v.y);
        __half2 hi = __floats2half2_rn(v.z, v.w);
        uint2 o;
        o.x = *reinterpret_cast<uint32_t*>(&lo);
        o.y = *reinterpret_cast<uint32_t*>(&hi);
        dst[i] = o;
    }
}

// ---------------- main GEMM: 2 N-tiles per CTA, one continuous pipeline ----------------
__global__ void __launch_bounds__(NTHREADS, 1)
indexed_dense_gemm(const float* __restrict__ bs, const int* __restrict__ index,
                   float* __restrict__ out) {
    extern __shared__ char smem[];
    const uint32_t sbase = smem_u32(smem);
    float* const smf = reinterpret_cast<float*>(smem);

    const int tid   = threadIdx.x;
    const int batch = blockIdx.z;
    const int m0    = blockIdx.y * BM;
    const int n0p   = blockIdx.x * (2 * BN);     // pair base
    const int e     = index[batch];

    // bias for both tiles (512 floats)
    smf[BIAS_OFF / 4 + tid]       = bs[(size_t)e * Uo + n0p + tid];
    smf[BIAS_OFF / 4 + 256 + tid] = bs[(size_t)e * Uo + n0p + 256 + tid];

    const __half* __restrict__ xg  = g_x16 + ((size_t)batch * Sq + m0) * Dk;   // [m][k]
    const __half* __restrict__ wg0 = g_wsT + ((size_t)e * Uo + n0p) * Dk;      // tile0 [n][k]

    // loaders: rows of 128 halves = 16 x 16B chunks; 256 threads
    const int lr   = tid >> 4;          // base row 0..15
    const int lc16 = tid & 15;          // chunk in row
    const uint32_t a_s0 = sbase + (uint32_t)(lr * 272 + lc16 * 16);
    const uint32_t b_s0 = sbase + A_TILE_B + (uint32_t)(lr * 272 + lc16 * 16);

    // g = global iteration 0..15; tile = g>>3, kt = g&7, stage = g&1
    auto load_stage_g = [&](int g) {
        const int kt = g & (NK - 1);
        const uint32_t so = (uint32_t)(g & 1) * STG_BYTES;
        const __half* ag = xg + (size_t)lr * Dk + kt * BK + lc16 * 8;
        const __half* bg = wg0 + (size_t)((g >> 3) * BN + lr) * Dk + kt * BK + lc16 * 8;
#pragma unroll
        for (int j = 0; j < 8; j++)
            cp16(a_s0 + so + j * 16 * 272, ag + (size_t)j * 16 * Dk);
#pragma unroll
        for (int j = 0; j < 16; j++)
            cp16(b_s0 + so + j * 16 * 272, bg + (size_t)j * 16 * Dk);
    };

    load_stage_g(0); cp_commit();

    // 8 warps = 2 (m) x 4 (n); warp tile 64 x 64
    const int warp = tid >> 5;
    const int lane = tid & 31;
    const int wm   = (warp >> 2) * 64;
    const int wn   = (warp & 3) * 64;
    const int r    = lane >> 2;
    const int c    = lane & 3;

    float d[4][8][4];
#pragma unroll
    for (int mi = 0; mi < 4; mi++)
#pragma unroll
        for (int ni = 0; ni < 8; ni++)
#pragma unroll
            for (int j = 0; j < 4; j++) d[mi][ni][j] = 0.0f;

    // epilogue for tile p: bias + relu + streaming stores, then re-zero d
    auto epilogue = [&](int p) {
        const float* bias_s = smf + BIAS_OFF / 4 + p * 256 + wn;
        const int nbase = n0p + p * BN + wn;
#pragma unroll
        for (int mi = 0; mi < 4; mi++) {
#pragma unroll
            for (int rr = 0; rr < 2; rr++) {
                const int m = m0 + wm + mi * 16 + rr * 8 + r;
                float* op = out + ((size_t)batch * Sq + m) * Uo + nbase;
#pragma unroll
                for (int ni = 0; ni < 8; ni++) {
                    const int nl = ni * 8 + 2 * c;
                    float2 v;
                    v.x = fmaxf(d[mi][ni][2 * rr + 0] + bias_s[nl + 0], 0.0f);
                    v.y = fmaxf(d[mi][ni][2 * rr + 1] + bias_s[nl + 1], 0.0f);
                    stcs8(op + nl, v);
                }
            }
        }
    };

#pragma unroll 1
    for (int g = 0; g < 2 * NK; g++) {
        cp_wait<0>();
        __syncthreads();

        if (g + 1 < 2 * NK) load_stage_g(g + 1);
        cp_commit();   // uniform group counting

        const __half* sa = reinterpret_cast<const __half*>(
            smem + (size_t)(g & 1) * STG_BYTES);
        const __half* sb = sa + BM * ST_H;

#pragma unroll
        for (int ks = 0; ks < 8; ks++) {
            const int k = ks * 16;
            uint32_t a[4][4];
#pragma unroll
            for (int mi = 0; mi < 4; mi++) {
                const int row = wm + mi * 16 + r;
                a[mi][0] = *reinterpret_cast<const uint32_t*>(&sa[(size_t)row * ST_H + k + 2 * c]);
                a[mi][1] = *reinterpret_cast<const uint32_t*>(&sa[(size_t)(row + 8) * ST_H + k + 2 * c]);
                a[mi][2] = *reinterpret_cast<const uint32_t*>(&sa[(size_t)row * ST_H + k + 2 * c + 8]);
                a[mi][3] = *reinterpret_cast<const uint32_t*>(&sa[(size_t)(row + 8) * ST_H + k + 2 * c + 8]);
            }
            uint32_t b[8][2];
#pragma unroll
            for (int ni = 0; ni < 8; ni++) {
                const int col = wn + ni * 8 + r;
                b[ni][0] = *reinterpret_cast<const uint32_t*>(&sb[(size_t)col * ST_H + k + 2 * c]);
                b[ni][1] = *reinterpret_cast<const uint32_t*>(&sb[(size_t)col * ST_H + k + 2 * c + 8]);
            }
#pragma unroll
            for (int mi = 0; mi < 4; mi++)
#pragma unroll
                for (int ni = 0; ni < 8; ni++)
                    mma_f16(d[mi][ni], a[mi], b[ni]);
        }

        if (g == NK - 1) {
            // tile 0 done; its epilogue overlaps tile 1's in-flight first loads
            epilogue(0);
#pragma unroll
            for (int mi = 0; mi < 4; mi++)
#pragma unroll
                for (int ni = 0; ni < 8; ni++)
#pragma unroll
                    for (int j = 0; j < 4; j++) d[mi][ni][j] = 0.0f;
        }
    }

    epilogue(1);
}

// ---------------- launch ----------------
extern "C" void kernel_launch(void* const* d_in, const int* in_sizes, int n_in,
                              void* d_out, int out_size) {
    const float* x     = (const float*)d_in[0];
    const float* ws    = (const float*)d_in[1];
    const float* bs    = (const float*)d_in[2];
    const int*   index = (const int*)d_in[3];
    float*       out   = (float*)d_out;
    (void)in_sizes; (void)n_in; (void)out_size;

    __half* x16_ptr = nullptr;
    cudaGetSymbolAddress((void**)&x16_ptr, g_x16);

    transpose_h_kernel<<<dim3(Uo / 32, Dk / 64, Ex), 256>>>(ws);
    const size_t x_n4 = (size_t)Bn * Sq * Dk / 4;
    cvt_h_kernel<<<4096, 256>>>((const float4*)x, (uint2*)x16_ptr, x_n4);

    static bool attr_set = false;
    if (!attr_set) {
        cudaFuncSetAttribute(indexed_dense_gemm,
                             cudaFuncAttributeMaxDynamicSharedMemorySize, SMEM_REQ);
        attr_set = true;
    }

    // grid: 8 n-pairs x 4 m-tiles x 64 batches = 2048 CTAs
    indexed_dense_gemm<<<dim3(Uo / (2 * BN), Sq / BM, Bn), NTHREADS, SMEM_REQ>>>(bs, index, out);
}

// round 16
// speedup vs baseline: 1.5215x; 1.5215x over previous
#include <cuda_runtime.h>
#include <cuda_fp16.h>
#include <cstdint>
#include <cstddef>

// Problem constants
#define Bn 64
#define Sq 512
#define Dk 1024
#define Uo 4096
#define Ex 16

// Tiling: CTA 128x256, warp 64x64 (8 warps = 2m x 4n), 256 threads, BK=128
#define BM 128
#define BN 256
#define BK 128
#define NK (Dk / BK)        // 8 K-tiles
#define NTHREADS 256
#define STAGES 2

// SMEM: halves, row stride 136 (272 B). Fragment LDS word = 68*row + c
// -> bank = (4*row + c) mod 32, conflict-free.
#define ST_H 136
#define A_TILE_B (BM * ST_H * 2)               // 34816
#define B_TILE_B (BN * ST_H * 2)               // 69632
#define STG_BYTES (A_TILE_B + B_TILE_B)        // 104448
#define BIAS_OFF (STAGES * STG_BYTES)          // 208896
#define SMEM_REQ (BIAS_OFF + BN * 4)           // 209920

// Device scratch: fp16 copies (x as-is, ws transposed to [e][n][k])
__device__ __half g_wsT[(size_t)Ex * Uo * Dk];   // 128 MB
__device__ __half g_x16[(size_t)Bn * Sq * Dk];   //  64 MB

// ---------------- helpers ----------------
__device__ __forceinline__ uint32_t smem_u32(const void* p) {
    uint32_t a;
    asm("{ .reg .u64 t; cvta.to.shared.u64 t, %1; cvt.u32.u64 %0, t; }"
        : "=r"(a) : "l"(p));
    return a;
}

__device__ __forceinline__ void cp16(uint32_t saddr, const void* g) {
    asm volatile("cp.async.cg.shared.global [%0], [%1], 16;" :: "r"(saddr), "l"(g));
}
__device__ __forceinline__ void cp_commit() {
    asm volatile("cp.async.commit_group;" ::: "memory");
}
template <int N>
__device__ __forceinline__ void cp_wait() {
    asm volatile("cp.async.wait_group %0;" :: "n"(N) : "memory");
}

__device__ __forceinline__ void mma_f16(float* d, const uint32_t* a, const uint32_t* b) {
    asm volatile(
        "mma.sync.aligned.m16n8k16.row.col.f32.f16.f16.f32 "
        "{%0,%1,%2,%3}, {%4,%5,%6,%7}, {%8,%9}, {%0,%1,%2,%3};"
        : "+f"(d[0]), "+f"(d[1]), "+f"(d[2]), "+f"(d[3])
        : "r"(a[0]), "r"(a[1]), "r"(a[2]), "r"(a[3]), "r"(b[0]), "r"(b[1]));
}

__device__ __forceinline__ void stcs8(float* p, float2 v) {
    asm volatile("st.global.cs.v2.f32 [%0], {%1, %2};" :: "l"(p), "f"(v.x), "f"(v.y)
                 : "memory");
}

// ---------------- pre-pass 1: ws [e][k][n] fp32 -> g_wsT [e][n][k] fp16 ----------------
// 64k x 32n tile. Phase 1: thread reads 2 consecutive-k floats (same n), packs
// half2, one 32-bit smem write. tileT2 stride 37 uint32 -> bank (5n+kp) mod 32,
// conflict-free. Phase 2: 16B reads per n-row, full 128B-line stores.
__global__ void __launch_bounds__(256) transpose_h_kernel(const float* __restrict__ ws) {
    __shared__ uint32_t tileT2[32][37];   // [n][kpair]
    const int e  = blockIdx.z;
    const int k0 = blockIdx.y * 64;
    const int n0 = blockIdx.x * 32;
    const int t  = threadIdx.x;

    const float* src = ws + ((size_t)e * Dk + k0) * Uo + n0;
    const int n  = t & 31;
    const int kp = t >> 5;               // 0..7
#pragma unroll
    for (int p = 0; p < 4; p++) {
        const int kk = (kp + p * 8) * 2;
        float v0 = src[(size_t)kk * Uo + n];
        float v1 = src[(size_t)(kk + 1) * Uo + n];
        __half2 h = __floats2half2_rn(v0, v1);
        tileT2[n][kp + p * 8] = *reinterpret_cast<uint32_t*>(&h);
    }
    __syncthreads();

    const int nn = t >> 3;               // 0..31
    const int j  = t & 7;                // 16B chunk in k
    __half* dst = g_wsT + ((size_t)e * Uo + n0 + nn) * Dk + k0;
    uint4 w;
    w.x = tileT2[nn][j * 4 + 0];
    w.y = tileT2[nn][j * 4 + 1];
    w.z = tileT2[nn][j * 4 + 2];
    w.w = tileT2[nn][j * 4 + 3];
    *reinterpret_cast<uint4*>(dst + j * 8) = w;
}

// ---------------- pre-pass 2: x fp32 -> fp16 ----------------
__global__ void __launch_bounds__(256) cvt_h_kernel(const float4* __restrict__ src,
                                                    uint2* __restrict__ dst, size_t n4) {
    size_t i = (size_t)blockIdx.x * blockDim.x + threadIdx.x;
    size_t stride = (size_t)gridDim.x * blockDim.x;
    for (; i < n4; i += stride) {
        float4 v = src[i];
        __half2 lo = __floats2half2_rn(v.x, v.y);
        __half2 hi = __floats2half2_rn(v.z, v.w);
        uint2 o;
        o.x = *reinterpret_cast<uint32_t*>(&lo);
        o.y = *reinterpret_cast<uint32_t*>(&hi);
        dst[i] = o;
    }
}

// ---------------- main GEMM: BK=128, 2 stages, 8 warps (2m x 4n), 1 CTA/SM ----------------
__global__ void __launch_bounds__(NTHREADS, 1)
indexed_dense_gemm(const float* __restrict__ bs, const int* __restrict__ index,
                   float* __restrict__ out) {
    extern __shared__ char smem[];
    const uint32_t sbase = smem_u32(smem);
    float* const smf = reinterpret_cast<float*>(smem);

    const int tid   = threadIdx.x;
    const int batch = blockIdx.z;
    const int m0    = blockIdx.y * BM;
    const int n0    = blockIdx.x * BN;
    const int e     = index[batch];

    smf[BIAS_OFF / 4 + tid] = bs[(size_t)e * Uo + n0 + tid];

    const __half* __restrict__ xg = g_x16 + ((size_t)batch * Sq + m0) * Dk;  // [m][k]
    const __half* __restrict__ wg = g_wsT + ((size_t)e * Uo + n0) * Dk;      // [n][k]

    // loaders: rows of 128 halves = 16 x 16B chunks; 256 threads
    const int lr   = tid >> 4;          // base row 0..15
    const int lc16 = tid & 15;          // chunk in row
    const uint32_t a_s0 = sbase + (uint32_t)(lr * 272 + lc16 * 16);
    const uint32_t b_s0 = sbase + A_TILE_B + (uint32_t)(lr * 272 + lc16 * 16);

    auto load_stage = [&](int kt, int s) {
        const uint32_t so = (uint32_t)s * STG_BYTES;
        const __half* ag = xg + (size_t)lr * Dk + kt * BK + lc16 * 8;
        const __half* bg = wg + (size_t)lr * Dk + kt * BK + lc16 * 8;
        // A: 128 rows, 16 per pass
#pragma unroll
        for (int j = 0; j < 8; j++)
            cp16(a_s0 + so + j * 16 * 272, ag + (size_t)j * 16 * Dk);
        // B: 256 rows, 16 per pass
#pragma unroll
        for (int j = 0; j < 16; j++)
            cp16(b_s0 + so + j * 16 * 272, bg + (size_t)j * 16 * Dk);
    };

    load_stage(0, 0); cp_commit();

    // 8 warps = 2 (m) x 4 (n); warp tile 64 x 64
    const int warp = tid >> 5;
    const int lane = tid & 31;
    const int wm   = (warp >> 2) * 64;
    const int wn   = (warp & 3) * 64;
    const int r    = lane >> 2;
    const int c    = lane & 3;

    float d[4][8][4];
#pragma unroll
    for (int mi = 0; mi < 4; mi++)
#pragma unroll
        for (int ni = 0; ni < 8; ni++)
#pragma unroll
            for (int j = 0; j < 4; j++) d[mi][ni][j] = 0.0f;

#pragma unroll 1
    for (int kt = 0; kt < NK; kt++) {
        cp_wait<0>();
        __syncthreads();

        if (kt + 1 < NK) load_stage(kt + 1, (kt + 1) & 1);
        cp_commit();   // uniform group counting

        const __half* sa = reinterpret_cast<const __half*>(
            smem + (size_t)(kt & 1) * STG_BYTES);
        const __half* sb = sa + BM * ST_H;

#pragma unroll
        for (int ks = 0; ks < 8; ks++) {
            const int k = ks * 16;
            uint32_t a[4][4];
#pragma unroll
            for (int mi = 0; mi < 4; mi++) {
                const int row = wm + mi * 16 + r;
                a[mi][0] = *reinterpret_cast<const uint32_t*>(&sa[(size_t)row * ST_H + k + 2 * c]);
                a[mi][1] = *reinterpret_cast<const uint32_t*>(&sa[(size_t)(row + 8) * ST_H + k + 2 * c]);
                a[mi][2] = *reinterpret_cast<const uint32_t*>(&sa[(size_t)row * ST_H + k + 2 * c + 8]);
                a[mi][3] = *reinterpret_cast<const uint32_t*>(&sa[(size_t)(row + 8) * ST_H + k + 2 * c + 8]);
            }
            uint32_t b[8][2];
#pragma unroll
            for (int ni = 0; ni < 8; ni++) {
                const int col = wn + ni * 8 + r;
                b[ni][0] = *reinterpret_cast<const uint32_t*>(&sb[(size_t)col * ST_H + k + 2 * c]);
                b[ni][1] = *reinterpret_cast<const uint32_t*>(&sb[(size_t)col * ST_H + k + 2 * c + 8]);
            }
#pragma unroll
            for (int mi = 0; mi < 4; mi++)
#pragma unroll
                for (int ni = 0; ni < 8; ni++)
                    mma_f16(d[mi][ni], a[mi], b[ni]);
        }
    }

    // epilogue: bias + relu + streaming float2 stores
    const float* bias_s = smf + BIAS_OFF / 4 + wn;
#pragma unroll
    for (int mi = 0; mi < 4; mi++) {
#pragma unroll
        for (int rr = 0; rr < 2; rr++) {
            const int m = m0 + wm + mi * 16 + rr * 8 + r;
            float* op = out + ((size_t)batch * Sq + m) * Uo + n0 + wn;
#pragma unroll
            for (int ni = 0; ni < 8; ni++) {
                const int nl = ni * 8 + 2 * c;
                float2 v;
                v.x = fmaxf(d[mi][ni][2 * rr + 0] + bias_s[nl + 0], 0.0f);
                v.y = fmaxf(d[mi][ni][2 * rr + 1] + bias_s[nl + 1], 0.0f);
                stcs8(op + nl, v);
            }
        }
    }
}

// ---------------- launch ----------------
extern "C" void kernel_launch(void* const* d_in, const int* in_sizes, int n_in,
                              void* d_out, int out_size) {
    const float* x     = (const float*)d_in[0];
    const float* ws    = (const float*)d_in[1];
    const float* bs    = (const float*)d_in[2];
    const int*   index = (const int*)d_in[3];
    float*       out   = (float*)d_out;
    (void)in_sizes; (void)n_in; (void)out_size;

    __half* x16_ptr = nullptr;
    cudaGetSymbolAddress((void**)&x16_ptr, g_x16);

    transpose_h_kernel<<<dim3(Uo / 32, Dk / 64, Ex), 256>>>(ws);
    const size_t x_n4 = (size_t)Bn * Sq * Dk / 4;
    cvt_h_kernel<<<4096, 256>>>((const float4*)x, (uint2*)x16_ptr, x_n4);

    static bool attr_set = false;
    if (!attr_set) {
        cudaFuncSetAttribute(indexed_dense_gemm,
                             cudaFuncAttributeMaxDynamicSharedMemorySize, SMEM_REQ);
        attr_set = true;
    }

    indexed_dense_gemm<<<dim3(Uo / BN, Sq / BM, Bn), NTHREADS, SMEM_REQ>>>(bs, index, out);
}

// round 17
// speedup vs baseline: 1.5314x; 1.0065x over previous
#include <cuda_runtime.h>
#include <cuda_fp16.h>
#include <cstdint>
#include <cstddef>

// Problem constants
#define Bn 64
#define Sq 512
#define Dk 1024
#define Uo 4096
#define Ex 16

// Tiling: CTA 128x256, warp 64x64 (8 warps = 2m x 4n), 256 threads, BK=128
#define BM 128
#define BN 256
#define BK 128
#define NK (Dk / BK)        // 8 K-tiles
#define NTHREADS 256
#define STAGES 2

// SMEM: halves, row stride 136 (272 B). Fragment LDS word = 68*row + c
// -> bank = (4*row + c) mod 32, conflict-free.
#define ST_H 136
#define A_TILE_B (BM * ST_H * 2)               // 34816
#define B_TILE_B (BN * ST_H * 2)               // 69632
#define STG_BYTES (A_TILE_B + B_TILE_B)        // 104448
#define BIAS_OFF (STAGES * STG_BYTES)          // 208896
#define SMEM_REQ (BIAS_OFF + BN * 4)           // 209920

// Pre-pass block split
#define TR_BLOCKS 32768                         // (Uo/32)*(Dk/64)*Ex
#define CVT_BLOCKS 4096
#define PRE_BLOCKS (TR_BLOCKS + CVT_BLOCKS)

// Device scratch: fp16 copies (x as-is, ws transposed to [e][n][k])
__device__ __half g_wsT[(size_t)Ex * Uo * Dk];   // 128 MB
__device__ __half g_x16[(size_t)Bn * Sq * Dk];   //  64 MB

// ---------------- helpers ----------------
__device__ __forceinline__ uint32_t smem_u32(const void* p) {
    uint32_t a;
    asm("{ .reg .u64 t; cvta.to.shared.u64 t, %1; cvt.u32.u64 %0, t; }"
        : "=r"(a) : "l"(p));
    return a;
}

__device__ __forceinline__ void cp16(uint32_t saddr, const void* g) {
    asm volatile("cp.async.cg.shared.global [%0], [%1], 16;" :: "r"(saddr), "l"(g));
}
__device__ __forceinline__ void cp_commit() {
    asm volatile("cp.async.commit_group;" ::: "memory");
}
template <int N>
__device__ __forceinline__ void cp_wait() {
    asm volatile("cp.async.wait_group %0;" :: "n"(N) : "memory");
}

__device__ __forceinline__ void mma_f16(float* d, const uint32_t* a, const uint32_t* b) {
    asm volatile(
        "mma.sync.aligned.m16n8k16.row.col.f32.f16.f16.f32 "
        "{%0,%1,%2,%3}, {%4,%5,%6,%7}, {%8,%9}, {%0,%1,%2,%3};"
        : "+f"(d[0]), "+f"(d[1]), "+f"(d[2]), "+f"(d[3])
        : "r"(a[0]), "r"(a[1]), "r"(a[2]), "r"(a[3]), "r"(b[0]), "r"(b[1]));
}

__device__ __forceinline__ void stcs8(float* p, float2 v) {
    asm volatile("st.global.cs.v2.f32 [%0], {%1, %2};" :: "l"(p), "f"(v.x), "f"(v.y)
                 : "memory");
}

// ---------------- merged pre-pass: transpose ws + convert x, one launch ----------------
// Blocks [0, TR_BLOCKS): ws [e][k][n] fp32 -> g_wsT [e][n][k] fp16 (64k x 32n tiles,
//   smem stride-37 conflict-free, full 128B-line stores).
// Blocks [TR_BLOCKS, PRE_BLOCKS): x fp32 -> g_x16 fp16, grid-stride float4.
__global__ void __launch_bounds__(256) prepass_kernel(const float* __restrict__ ws,
                                                      const float4* __restrict__ x4) {
    __shared__ uint32_t tileT2[32][37];   // [n][kpair], bank (5n+kp)%32, conflict-free
    const int bid = blockIdx.x;
    const int t   = threadIdx.x;

    if (bid < TR_BLOCKS) {
        // decompose: x (n-tile) fastest [128], then y (k-tile) [16], then e [16]
        const int xb = bid & 127;
        const int yb = (bid >> 7) & 15;
        const int e  = bid >> 11;
        const int k0 = yb * 64;
        const int n0 = xb * 32;

        const float* src = ws + ((size_t)e * Dk + k0) * Uo + n0;
        const int n  = t & 31;
        const int kp = t >> 5;               // 0..7
#pragma unroll
        for (int p = 0; p < 4; p++) {
            const int kk = (kp + p * 8) * 2;
            float v0 = src[(size_t)kk * Uo + n];
            float v1 = src[(size_t)(kk + 1) * Uo + n];
            __half2 h = __floats2half2_rn(v0, v1);
            tileT2[n][kp + p * 8] = *reinterpret_cast<uint32_t*>(&h);
        }
        __syncthreads();

        const int nn = t >> 3;               // 0..31
        const int j  = t & 7;                // 16B chunk in k
        __half* dst = g_wsT + ((size_t)e * Uo + n0 + nn) * Dk + k0;
        uint4 w;
        w.x = tileT2[nn][j * 4 + 0];
        w.y = tileT2[nn][j * 4 + 1];
        w.z = tileT2[nn][j * 4 + 2];
        w.w = tileT2[nn][j * 4 + 3];
        *reinterpret_cast<uint4*>(dst + j * 8) = w;
    } else {
        const size_t n4 = (size_t)Bn * Sq * Dk / 4;   // 8,388,608 float4
        uint2* dst = reinterpret_cast<uint2*>(g_x16);
        size_t i = (size_t)(bid - TR_BLOCKS) * 256 + t;
        const size_t stride = (size_t)CVT_BLOCKS * 256;
        for (; i < n4; i += stride) {
            float4 v = x4[i];
            __half2 lo = __floats2half2_rn(v.x, v.y);
            __half2 hi = __floats2half2_rn(v.z, v.w);
            uint2 o;
            o.x = *reinterpret_cast<uint32_t*>(&lo);
            o.y = *reinterpret_cast<uint32_t*>(&hi);
            dst[i] = o;
        }
    }
}

// ---------------- main GEMM: BK=128, 2 stages, 8 warps (2m x 4n), 1 CTA/SM ----------------
// (byte-identical to the verified 903.6us configuration)
__global__ void __launch_bounds__(NTHREADS, 1)
indexed_dense_gemm(const float* __restrict__ bs, const int* __restrict__ index,
                   float* __restrict__ out) {
    extern __shared__ char smem[];
    const uint32_t sbase = smem_u32(smem);
    float* const smf = reinterpret_cast<float*>(smem);

    const int tid   = threadIdx.x;
    const int batch = blockIdx.z;
    const int m0    = blockIdx.y * BM;
    const int n0    = blockIdx.x * BN;
    const int e     = index[batch];

    smf[BIAS_OFF / 4 + tid] = bs[(size_t)e * Uo + n0 + tid];

    const __half* __restrict__ xg = g_x16 + ((size_t)batch * Sq + m0) * Dk;  // [m][k]
    const __half* __restrict__ wg = g_wsT + ((size_t)e * Uo + n0) * Dk;      // [n][k]

    // loaders: rows of 128 halves = 16 x 16B chunks; 256 threads
    const int lr   = tid >> 4;          // base row 0..15
    const int lc16 = tid & 15;          // chunk in row
    const uint32_t a_s0 = sbase + (uint32_t)(lr * 272 + lc16 * 16);
    const uint32_t b_s0 = sbase + A_TILE_B + (uint32_t)(lr * 272 + lc16 * 16);

    auto load_stage = [&](int kt, int s) {
        const uint32_t so = (uint32_t)s * STG_BYTES;
        const __half* ag = xg + (size_t)lr * Dk + kt * BK + lc16 * 8;
        const __half* bg = wg + (size_t)lr * Dk + kt * BK + lc16 * 8;
        // A: 128 rows, 16 per pass
#pragma unroll
        for (int j = 0; j < 8; j++)
            cp16(a_s0 + so + j * 16 * 272, ag + (size_t)j * 16 * Dk);
        // B: 256 rows, 16 per pass
#pragma unroll
        for (int j = 0; j < 16; j++)
            cp16(b_s0 + so + j * 16 * 272, bg + (size_t)j * 16 * Dk);
    };

    load_stage(0, 0); cp_commit();

    // 8 warps = 2 (m) x 4 (n); warp tile 64 x 64
    const int warp = tid >> 5;
    const int lane = tid & 31;
    const int wm   = (warp >> 2) * 64;
    const int wn   = (warp & 3) * 64;
    const int r    = lane >> 2;
    const int c    = lane & 3;

    float d[4][8][4];
#pragma unroll
    for (int mi = 0; mi < 4; mi++)
#pragma unroll
        for (int ni = 0; ni < 8; ni++)
#pragma unroll
            for (int j = 0; j < 4; j++) d[mi][ni][j] = 0.0f;

#pragma unroll 1
    for (int kt = 0; kt < NK; kt++) {
        cp_wait<0>();
        __syncthreads();

        if (kt + 1 < NK) load_stage(kt + 1, (kt + 1) & 1);
        cp_commit();   // uniform group counting

        const __half* sa = reinterpret_cast<const __half*>(
            smem + (size_t)(kt & 1) * STG_BYTES);
        const __half* sb = sa + BM * ST_H;

#pragma unroll
        for (int ks = 0; ks < 8; ks++) {
            const int k = ks * 16;
            uint32_t a[4][4];
#pragma unroll
            for (int mi = 0; mi < 4; mi++) {
                const int row = wm + mi * 16 + r;
                a[mi][0] = *reinterpret_cast<const uint32_t*>(&sa[(size_t)row * ST_H + k + 2 * c]);
                a[mi][1] = *reinterpret_cast<const uint32_t*>(&sa[(size_t)(row + 8) * ST_H + k + 2 * c]);
                a[mi][2] = *reinterpret_cast<const uint32_t*>(&sa[(size_t)row * ST_H + k + 2 * c + 8]);
                a[mi][3] = *reinterpret_cast<const uint32_t*>(&sa[(size_t)(row + 8) * ST_H + k + 2 * c + 8]);
            }
            uint32_t b[8][2];
#pragma unroll
            for (int ni = 0; ni < 8; ni++) {
                const int col = wn + ni * 8 + r;
                b[ni][0] = *reinterpret_cast<const uint32_t*>(&sb[(size_t)col * ST_H + k + 2 * c]);
                b[ni][1] = *reinterpret_cast<const uint32_t*>(&sb[(size_t)col * ST_H + k + 2 * c + 8]);
            }
#pragma unroll
            for (int mi = 0; mi < 4; mi++)
#pragma unroll
                for (int ni = 0; ni < 8; ni++)
                    mma_f16(d[mi][ni], a[mi], b[ni]);
        }
    }

    // epilogue: bias + relu + streaming float2 stores
    const float* bias_s = smf + BIAS_OFF / 4 + wn;
#pragma unroll
    for (int mi = 0; mi < 4; mi++) {
#pragma unroll
        for (int rr = 0; rr < 2; rr++) {
            const int m = m0 + wm + mi * 16 + rr * 8 + r;
            float* op = out + ((size_t)batch * Sq + m) * Uo + n0 + wn;
#pragma unroll
            for (int ni = 0; ni < 8; ni++) {
                const int nl = ni * 8 + 2 * c;
                float2 v;
                v.x = fmaxf(d[mi][ni][2 * rr + 0] + bias_s[nl + 0], 0.0f);
                v.y = fmaxf(d[mi][ni][2 * rr + 1] + bias_s[nl + 1], 0.0f);
                stcs8(op + nl, v);
            }
        }
    }
}

// ---------------- launch ----------------
extern "C" void kernel_launch(void* const* d_in, const int* in_sizes, int n_in,
                              void* d_out, int out_size) {
    const float* x     = (const float*)d_in[0];
    const float* ws    = (const float*)d_in[1];
    const float* bs    = (const float*)d_in[2];
    const int*   index = (const int*)d_in[3];
    float*       out   = (float*)d_out;
    (void)in_sizes; (void)n_in; (void)out_size;

    // single merged pre-pass launch: ws transpose+cvt and x cvt
    prepass_kernel<<<PRE_BLOCKS, 256>>>(ws, (const float4*)x);

    static bool attr_set = false;
    if (!attr_set) {
        cudaFuncSetAttribute(indexed_dense_gemm,
                             cudaFuncAttributeMaxDynamicSharedMemorySize, SMEM_REQ);
        attr_set = true;
    }

    indexed_dense_gemm<<<dim3(Uo / BN, Sq / BM, Bn), NTHREADS, SMEM_REQ>>>(bs, index, out);
}